// round 12
// baseline (speedup 1.0000x reference)
#include <cuda_runtime.h>
#include <cuda_bf16.h>
#include <stdint.h>

// SLAM_Layer: fused per-t 3-GEMM chain on mma.sync (bf16 HMMA), 2-term bf16 split.
//   Phase1: H   = relu(X_t @ W1 + b1)      D1[m][d], M=128 K=64  N=128
//   Phase2: S^T = W2^T @ H^T (+b2)         D2[k][m], M=128 K=128 N=128
//   Phase3: out = main_t @ S               D3[i][k], M=128 K=128 N=128 (B = S^T)
// R12 = R10 (16 warps, 4x4 grid, 32x32 tiles — best config) +
//   cp.async weight copies, main-tile build moved after epilogue1 (overlaps
//   barrier/epilogue tail with DRAM latency), prologue load-ordering.

#define TPB 512
#define SETUP_TPB 256
static constexpr int Tn = 1024;

// dynamic smem byte offsets
static constexpr uint32_t OFF_XHI   = 0;        // 16KB
static constexpr uint32_t OFF_XLO   = 16384;
static constexpr uint32_t OFF_W1T   = 32768;    // hi 16KB + lo 16KB
static constexpr uint32_t OFF_W1THI = 32768;
static constexpr uint32_t OFF_W1TLO = 49152;
static constexpr uint32_t OFF_HHI   = 0;        // 32KB (over X/W1T after phase1)
static constexpr uint32_t OFF_HLO   = 32768;
static constexpr uint32_t OFF_W2T   = 65536;    // hi 32KB + lo 32KB
static constexpr uint32_t OFF_W2THI = 65536;
static constexpr uint32_t OFF_W2TLO = 98304;
static constexpr uint32_t OFF_STHI  = 65536;    // over W2T after phase2
static constexpr uint32_t OFF_STLO  = 98304;
static constexpr uint32_t OFF_MHI   = 131072;   // 32KB
static constexpr uint32_t OFF_MLO   = 163840;
static constexpr uint32_t DYN_BYTES = 196608 + 1024;

// pre-split, pre-swizzled weight tiles (rewritten by setup kernel each call)
__device__ __align__(16) uint8_t g_w1t[32768];   // W1^T: hi [0,16K), lo [16K,32K)
__device__ __align__(16) uint8_t g_w2t[65536];   // W2^T: hi [0,32K), lo [32K,64K)

__device__ __forceinline__ uint32_t smem_u32(const void* p) {
    uint32_t a;
    asm("{ .reg .u64 t; cvta.to.shared.u64 t, %1; cvt.u32.u64 %0, t; }" : "=r"(a) : "l"(p));
    return a;
}

// SW128-style swizzle (writer and reader share these; bank-behavior only)
__device__ __forceinline__ uint32_t swz(uint32_t b) { return b ^ ((b >> 3) & 0x70); }
__device__ __forceinline__ uint32_t k64_off(int r, int c) {   // 128 rows x 64 bf16
    return swz((uint32_t)(r * 128 + c * 2));
}
__device__ __forceinline__ uint32_t k128_off(int r, int c) {  // 128 rows x 128 bf16
    return swz(((uint32_t)(c >> 6) << 14) + ((uint32_t)(r >> 3) << 10) +
               ((uint32_t)(r & 7) << 7) + ((uint32_t)(c & 63) << 1));
}

__device__ __forceinline__ void split_bf(float f, __nv_bfloat16& h, __nv_bfloat16& l) {
    h = __float2bfloat16_rn(f);
    l = __float2bfloat16_rn(f - __bfloat162float(h));
}
__device__ __forceinline__ void split2(float f0, float f1, uint32_t& hi, uint32_t& lo) {
    __nv_bfloat16 h0, l0, h1, l1;
    split_bf(f0, h0, l0); split_bf(f1, h1, l1);
    __nv_bfloat162 H; H.x = h0; H.y = h1;
    __nv_bfloat162 L; L.x = l0; L.y = l1;
    hi = *(uint32_t*)&H; lo = *(uint32_t*)&L;
}
__device__ __forceinline__ void split4(float4 v, uint2& hi, uint2& lo) {
    uint32_t h01, l01, h23, l23;
    split2(v.x, v.y, h01, l01);
    split2(v.z, v.w, h23, l23);
    hi.x = h01; hi.y = h23; lo.x = l01; lo.y = l23;
}

#define LDSM4(r, addr)                                                          \
    asm volatile("ldmatrix.sync.aligned.m8n8.x4.shared.b16 {%0,%1,%2,%3}, [%4];"\
        : "=r"((r)[0]), "=r"((r)[1]), "=r"((r)[2]), "=r"((r)[3]) : "r"(addr))

#define STM4(addr, r)                                                           \
    asm volatile("stmatrix.sync.aligned.m8n8.x4.shared.b16 [%0], {%1,%2,%3,%4};"\
        :: "r"(addr), "r"((r)[0]), "r"((r)[1]), "r"((r)[2]), "r"((r)[3]) : "memory")

#define MMA16816(d, a, b0, b1)                                                  \
    asm volatile("mma.sync.aligned.m16n8k16.row.col.f32.bf16.bf16.f32 "         \
        "{%0,%1,%2,%3}, {%4,%5,%6,%7}, {%8,%9}, {%0,%1,%2,%3};"                 \
        : "+f"((d)[0]), "+f"((d)[1]), "+f"((d)[2]), "+f"((d)[3])                \
        : "r"((a)[0]), "r"((a)[1]), "r"((a)[2]), "r"((a)[3]), "r"(b0), "r"(b1))

#define CP16(dst, src)                                                          \
    asm volatile("cp.async.cg.shared.global [%0], [%1], 16;"                    \
        :: "r"(dst), "l"(src) : "memory")
#define CP_COMMIT() asm volatile("cp.async.commit_group;" ::: "memory")
#define CP_WAIT0()  asm volatile("cp.async.wait_group 0;" ::: "memory")

// One phase: D += 3 split terms of A @ B^T. Warp tile 32x32. Frags loaded once/k16.
template <int NK, bool K64>
__device__ __forceinline__ void gemm_phase(uint32_t sbase,
                                           uint32_t aHi, uint32_t aLo,
                                           uint32_t bHi, uint32_t bLo,
                                           int wr, int wc, int lane,
                                           float d[2][4][4]) {
    const int a_row = lane & 15, a_qp = lane >> 4;
    const int b_row = ((lane >> 4) << 3) + (lane & 7);
    const int b_qp  = (lane >> 3) & 1;
    const uint32_t AH = sbase + aHi, AL = sbase + aLo;
    const uint32_t BH = sbase + bHi, BL = sbase + bLo;

    #pragma unroll 2
    for (int ks = 0; ks < NK; ++ks) {
        const int ca = (2 * ks + a_qp) * 8;
        const int cb = (2 * ks + b_qp) * 8;
        uint32_t ah[2][4], al[2][4], bh[2][4], bl[2][4];
        #pragma unroll
        for (int mi = 0; mi < 2; ++mi) {
            int r = 32 * wr + 16 * mi + a_row;
            uint32_t off = K64 ? k64_off(r, ca) : k128_off(r, ca);
            LDSM4(ah[mi], AH + off);
            LDSM4(al[mi], AL + off);
        }
        #pragma unroll
        for (int nb = 0; nb < 2; ++nb) {
            int r = 32 * wc + 16 * nb + b_row;
            uint32_t off = K64 ? k64_off(r, cb) : k128_off(r, cb);
            LDSM4(bh[nb], BH + off);
            LDSM4(bl[nb], BL + off);
        }
        // term 0: hi*hi
        #pragma unroll
        for (int nb = 0; nb < 2; ++nb)
            #pragma unroll
            for (int mi = 0; mi < 2; ++mi) {
                MMA16816(d[mi][2 * nb],     ah[mi], bh[nb][0], bh[nb][1]);
                MMA16816(d[mi][2 * nb + 1], ah[mi], bh[nb][2], bh[nb][3]);
            }
        // term 1: hi*lo
        #pragma unroll
        for (int nb = 0; nb < 2; ++nb)
            #pragma unroll
            for (int mi = 0; mi < 2; ++mi) {
                MMA16816(d[mi][2 * nb],     ah[mi], bl[nb][0], bl[nb][1]);
                MMA16816(d[mi][2 * nb + 1], ah[mi], bl[nb][2], bl[nb][3]);
            }
        // term 2: lo*hi
        #pragma unroll
        for (int nb = 0; nb < 2; ++nb)
            #pragma unroll
            for (int mi = 0; mi < 2; ++mi) {
                MMA16816(d[mi][2 * nb],     al[mi], bh[nb][0], bh[nb][1]);
                MMA16816(d[mi][2 * nb + 1], al[mi], bh[nb][2], bh[nb][3]);
            }
    }
}

// ---- setup kernel: split + swizzle weights, PARALLEL (64 blocks) ----
__global__ void slam_setup(const float* __restrict__ gW1, const float* __restrict__ gW2)
{
    const int g = blockIdx.x * SETUP_TPB + threadIdx.x;   // 16384 threads
    if (g < 8192) {
        int a = g >> 7, dcol = g & 127;
        __nv_bfloat16 h, l; split_bf(gW1[g], h, l);
        uint32_t off = k64_off(dcol, a);
        *(__nv_bfloat16*)(g_w1t + off)         = h;
        *(__nv_bfloat16*)(g_w1t + 16384 + off) = l;
    }
    {
        int drow = g >> 7, k = g & 127;
        __nv_bfloat16 h, l; split_bf(gW2[g], h, l);
        uint32_t off = k128_off(k, drow);
        *(__nv_bfloat16*)(g_w2t + off)         = h;
        *(__nv_bfloat16*)(g_w2t + 32768 + off) = l;
    }
}

__global__ __launch_bounds__(TPB, 1)
void slam_mma(const float* __restrict__ x_main, const float* __restrict__ x_aux,
              const float* __restrict__ gb1, const float* __restrict__ gb2,
              float* __restrict__ out)
{
    extern __shared__ uint8_t dynraw[];
    __shared__ float sB1[128], sB2[128];

    uint8_t* dyn = (uint8_t*)(((uintptr_t)dynraw + 1023) & ~(uintptr_t)1023);
    const uint32_t sbase = smem_u32(dyn);
    const int t = blockIdx.x;
    const int tid = threadIdx.x, wid = tid >> 5, lane = tid & 31;
    const int wr = wid >> 2, wc = wid & 3;   // 4x4 warp grid, 32x32 tiles

    // 1) weight copies via cp.async (no register round-trip, overlaps X build)
    {
        uint32_t d1 = sbase + OFF_W1T + tid * 16;
        const uint8_t* s1 = g_w1t + tid * 16;
        #pragma unroll
        for (int i = 0; i < 4; i++) CP16(d1 + i * TPB * 16, s1 + i * TPB * 16);   // 32KB
        uint32_t d2 = sbase + OFF_W2T + tid * 16;
        const uint8_t* s2 = g_w2t + tid * 16;
        #pragma unroll
        for (int i = 0; i < 8; i++) CP16(d2 + i * TPB * 16, s2 + i * TPB * 16);   // 64KB
        CP_COMMIT();
    }
    if (tid < 128) { sB1[tid] = gb1[tid]; sB2[tid] = gb2[tid]; }

    // 2) X_t build: row m = 64 floats at x_aux + (m*T + t)*64  (K64 tile)
    #pragma unroll
    for (int i = 0; i < 4; i++) {
        int idx = tid + i * TPB;            // 2048 float4
        int m = idx >> 4, c = (idx & 15) * 4;
        float4 v = *(const float4*)(x_aux + ((size_t)m * Tn + t) * 64 + c);
        uint2 hi, lo; split4(v, hi, lo);
        uint32_t off = k64_off(m, c);
        *(uint2*)(dyn + OFF_XHI + off) = hi;
        *(uint2*)(dyn + OFF_XLO + off) = lo;
    }
    CP_WAIT0();
    __syncthreads();

    const int r_base = lane >> 2;             // D frag rows r_base / +8
    const int c_base = 2 * (lane & 3);        // D frag col pair
    const int st_h   = (lane >> 3) & 1;       // stmatrix lane->tile mapping
    const int st_nj  = lane >> 4;
    const int st_row = lane & 7;

    float d[2][4][4];

    // ---------------- Phase 1: D1[m][d] = X @ W1 ----------------
    #pragma unroll
    for (int mi = 0; mi < 2; ++mi)
        #pragma unroll
        for (int nj = 0; nj < 4; ++nj)
            #pragma unroll
            for (int q = 0; q < 4; ++q) d[mi][nj][q] = 0.f;

    gemm_phase<4, true>(sbase, OFF_XHI, OFF_XLO, OFF_W1THI, OFF_W1TLO, wr, wc, lane, d);
    __syncthreads();   // all warps done reading X/W1T before H overwrites them

    // Epilogue 1: +b1, relu, split -> H via stmatrix
    #pragma unroll
    for (int mi = 0; mi < 2; ++mi) {
        #pragma unroll
        for (int njp = 0; njp < 2; ++njp) {
            uint32_t hiR[4], loR[4];
            #pragma unroll
            for (int q = 0; q < 4; ++q) {           // q = (njoff<<1)|h
                int nj = 2 * njp + (q >> 1), h = q & 1;
                int col = 32 * wc + 8 * nj + c_base;
                float f0 = fmaxf(d[mi][nj][2 * h]     + sB1[col],     0.f);
                float f1 = fmaxf(d[mi][nj][2 * h + 1] + sB1[col + 1], 0.f);
                split2(f0, f1, hiR[q], loR[q]);
            }
            int row = 32 * wr + 16 * mi + 8 * st_h + st_row;
            int col = 32 * wc + 8 * (2 * njp + st_nj);
            uint32_t off = k128_off(row, col);
            STM4(sbase + OFF_HHI + off, hiR);
            STM4(sbase + OFF_HLO + off, loR);
        }
    }

    // main_t build moved here: independent of H/W2T, overlaps epilogue tail +
    // barrier-arrival spread with its DRAM latency. Region exclusive until phase3.
    {
        const float* mp = x_main + ((size_t)(3 * Tn + t)) * 16384;
        #pragma unroll
        for (int i = 0; i < 8; i++) {
            int idx = tid + i * TPB;        // 4096 float4
            int r = idx >> 5, c = (idx & 31) * 4;
            float4 v = *(const float4*)(mp + r * 128 + c);
            uint2 hi, lo; split4(v, hi, lo);
            uint32_t off = k128_off(r, c);
            *(uint2*)(dyn + OFF_MHI + off) = hi;
            *(uint2*)(dyn + OFF_MLO + off) = lo;
        }
    }
    __syncthreads();

    // ---------------- Phase 2: D2[k][m] = W2^T @ H^T = S^T ----------------
    #pragma unroll
    for (int mi = 0; mi < 2; ++mi)
        #pragma unroll
        for (int nj = 0; nj < 4; ++nj)
            #pragma unroll
            for (int q = 0; q < 4; ++q) d[mi][nj][q] = 0.f;

    gemm_phase<8, false>(sbase, OFF_W2THI, OFF_W2TLO, OFF_HHI, OFF_HLO, wr, wc, lane, d);
    __syncthreads();   // done reading W2T before S^T overwrites it

    // Epilogue 2: +b2[row k], split -> S^T via stmatrix
    #pragma unroll
    for (int mi = 0; mi < 2; ++mi) {
        const int rb = 32 * wr + 16 * mi + r_base;
        const float b2lo = sB2[rb], b2hi = sB2[rb + 8];
        #pragma unroll
        for (int njp = 0; njp < 2; ++njp) {
            uint32_t hiR[4], loR[4];
            #pragma unroll
            for (int q = 0; q < 4; ++q) {
                int nj = 2 * njp + (q >> 1), h = q & 1;
                float bias = h ? b2hi : b2lo;
                float f0 = d[mi][nj][2 * h]     + bias;
                float f1 = d[mi][nj][2 * h + 1] + bias;
                split2(f0, f1, hiR[q], loR[q]);
            }
            int row = 32 * wr + 16 * mi + 8 * st_h + st_row;
            int col = 32 * wc + 8 * (2 * njp + st_nj);
            uint32_t off = k128_off(row, col);
            STM4(sbase + OFF_STHI + off, hiR);
            STM4(sbase + OFF_STLO + off, loR);
        }
    }
    __syncthreads();

    // ---------------- Phase 3: D3[i][k] = main @ S (B = S^T) ----------------
    #pragma unroll
    for (int mi = 0; mi < 2; ++mi)
        #pragma unroll
        for (int nj = 0; nj < 4; ++nj)
            #pragma unroll
            for (int q = 0; q < 4; ++q) d[mi][nj][q] = 0.f;

    gemm_phase<8, false>(sbase, OFF_MHI, OFF_MLO, OFF_STHI, OFF_STLO, wr, wc, lane, d);

    // Epilogue 3: direct fp32 float2 stores to gmem
    float* outT = out + (size_t)t * 16384;
    #pragma unroll
    for (int mi = 0; mi < 2; ++mi) {
        #pragma unroll
        for (int nj = 0; nj < 4; ++nj) {
            int col = 32 * wc + 8 * nj + c_base;
            #pragma unroll
            for (int h = 0; h < 2; ++h) {
                int row = 32 * wr + 16 * mi + r_base + 8 * h;
                float2 v; v.x = d[mi][nj][2 * h]; v.y = d[mi][nj][2 * h + 1];
                *(float2*)&outT[row * 128 + col] = v;
            }
        }
    }
}

extern "C" void kernel_launch(void* const* d_in, const int* in_sizes, int n_in,
                              void* d_out, int out_size)
{
    const float* x_main = (const float*)d_in[0];
    const float* x_aux  = (const float*)d_in[1];
    const float* W1     = (const float*)d_in[2];
    const float* b1     = (const float*)d_in[3];
    const float* W2     = (const float*)d_in[4];
    const float* b2     = (const float*)d_in[5];
    float* out = (float*)d_out;

    slam_setup<<<64, SETUP_TPB>>>(W1, W2);
    cudaFuncSetAttribute(slam_mma, cudaFuncAttributeMaxDynamicSharedMemorySize, DYN_BYTES);
    slam_mma<<<1024, TPB, DYN_BYTES>>>(x_main, x_aux, b1, b2, out);
}

// round 13
// speedup vs baseline: 1.3758x; 1.3758x over previous
#include <cuda_runtime.h>
#include <cuda_bf16.h>
#include <stdint.h>

// SLAM_Layer: fused per-t 3-GEMM chain on mma.sync (bf16 HMMA), 2-term bf16 split.
//   Phase1: H   = relu(X_t @ W1 + b1)      D1[m][d], M=128 K=64  N=128
//   Phase2: S^T = W2^T @ H^T (+b2)         D2[k][m], M=128 K=128 N=128
//   Phase3: out = main_t @ S               D3[i][k], M=128 K=128 N=128 (B = S^T)
// R13 = R10 body (16 warps, 4x4 grid, 32x32 tiles, LDG/STS weight copy — best
// config) made PERSISTENT: grid=152, each block loops over ~7 t values with the
// 96KB weight tiles copied to smem ONCE and kept resident. New layout:
//   W1T 32K | W2T 64K | U 64K (X -> H -> S^T overlay) | M 64K  = 224KB.

#define TPB 512
#define SETUP_TPB 256
#define GRID 152
static constexpr int Tn = 1024;

// dynamic smem byte offsets (weights resident across the whole block)
static constexpr uint32_t OFF_W1THI = 0;        // 16KB
static constexpr uint32_t OFF_W1TLO = 16384;    // 16KB
static constexpr uint32_t OFF_W1T   = 0;        // copy target (32KB contiguous)
static constexpr uint32_t OFF_W2THI = 32768;    // 32KB
static constexpr uint32_t OFF_W2TLO = 65536;    // 32KB
static constexpr uint32_t OFF_W2T   = 32768;    // copy target (64KB contiguous)
// U region: X (phase1) -> H (epi1..phase2) -> S^T (epi2..phase3), 64KB
static constexpr uint32_t OFF_XHI   = 98304;    // 16KB
static constexpr uint32_t OFF_XLO   = 114688;   // 16KB
static constexpr uint32_t OFF_HHI   = 98304;    // 32KB (overlays X after phase1)
static constexpr uint32_t OFF_HLO   = 131072;   // 32KB
static constexpr uint32_t OFF_STHI  = 98304;    // 32KB (overlays H after phase2)
static constexpr uint32_t OFF_STLO  = 131072;   // 32KB
// M region: main_t tile, 64KB
static constexpr uint32_t OFF_MHI   = 163840;   // 32KB
static constexpr uint32_t OFF_MLO   = 196608;   // 32KB
static constexpr uint32_t DYN_BYTES = 229376 + 1024;   // 224KB + alignment pad

// pre-split, pre-swizzled weight tiles (rewritten by setup kernel each call)
__device__ __align__(16) uint8_t g_w1t[32768];   // W1^T: hi [0,16K), lo [16K,32K)
__device__ __align__(16) uint8_t g_w2t[65536];   // W2^T: hi [0,32K), lo [32K,64K)

__device__ __forceinline__ uint32_t smem_u32(const void* p) {
    uint32_t a;
    asm("{ .reg .u64 t; cvta.to.shared.u64 t, %1; cvt.u32.u64 %0, t; }" : "=r"(a) : "l"(p));
    return a;
}

// SW128-style swizzle (writer and reader share these; bank-behavior only)
__device__ __forceinline__ uint32_t swz(uint32_t b) { return b ^ ((b >> 3) & 0x70); }
__device__ __forceinline__ uint32_t k64_off(int r, int c) {   // 128 rows x 64 bf16
    return swz((uint32_t)(r * 128 + c * 2));
}
__device__ __forceinline__ uint32_t k128_off(int r, int c) {  // 128 rows x 128 bf16
    return swz(((uint32_t)(c >> 6) << 14) + ((uint32_t)(r >> 3) << 10) +
               ((uint32_t)(r & 7) << 7) + ((uint32_t)(c & 63) << 1));
}

__device__ __forceinline__ void split_bf(float f, __nv_bfloat16& h, __nv_bfloat16& l) {
    h = __float2bfloat16_rn(f);
    l = __float2bfloat16_rn(f - __bfloat162float(h));
}
__device__ __forceinline__ void split2(float f0, float f1, uint32_t& hi, uint32_t& lo) {
    __nv_bfloat16 h0, l0, h1, l1;
    split_bf(f0, h0, l0); split_bf(f1, h1, l1);
    __nv_bfloat162 H; H.x = h0; H.y = h1;
    __nv_bfloat162 L; L.x = l0; L.y = l1;
    hi = *(uint32_t*)&H; lo = *(uint32_t*)&L;
}
__device__ __forceinline__ void split4(float4 v, uint2& hi, uint2& lo) {
    uint32_t h01, l01, h23, l23;
    split2(v.x, v.y, h01, l01);
    split2(v.z, v.w, h23, l23);
    hi.x = h01; hi.y = h23; lo.x = l01; lo.y = l23;
}

#define LDSM4(r, addr)                                                          \
    asm volatile("ldmatrix.sync.aligned.m8n8.x4.shared.b16 {%0,%1,%2,%3}, [%4];"\
        : "=r"((r)[0]), "=r"((r)[1]), "=r"((r)[2]), "=r"((r)[3]) : "r"(addr))

#define STM4(addr, r)                                                           \
    asm volatile("stmatrix.sync.aligned.m8n8.x4.shared.b16 [%0], {%1,%2,%3,%4};"\
        :: "r"(addr), "r"((r)[0]), "r"((r)[1]), "r"((r)[2]), "r"((r)[3]) : "memory")

#define MMA16816(d, a, b0, b1)                                                  \
    asm volatile("mma.sync.aligned.m16n8k16.row.col.f32.bf16.bf16.f32 "         \
        "{%0,%1,%2,%3}, {%4,%5,%6,%7}, {%8,%9}, {%0,%1,%2,%3};"                 \
        : "+f"((d)[0]), "+f"((d)[1]), "+f"((d)[2]), "+f"((d)[3])                \
        : "r"((a)[0]), "r"((a)[1]), "r"((a)[2]), "r"((a)[3]), "r"(b0), "r"(b1))

// One phase: D += 3 split terms of A @ B^T. Warp tile 32x32. Frags loaded once/k16.
template <int NK, bool K64>
__device__ __forceinline__ void gemm_phase(uint32_t sbase,
                                           uint32_t aHi, uint32_t aLo,
                                           uint32_t bHi, uint32_t bLo,
                                           int wr, int wc, int lane,
                                           float d[2][4][4]) {
    const int a_row = lane & 15, a_qp = lane >> 4;
    const int b_row = ((lane >> 4) << 3) + (lane & 7);
    const int b_qp  = (lane >> 3) & 1;
    const uint32_t AH = sbase + aHi, AL = sbase + aLo;
    const uint32_t BH = sbase + bHi, BL = sbase + bLo;

    #pragma unroll 2
    for (int ks = 0; ks < NK; ++ks) {
        const int ca = (2 * ks + a_qp) * 8;
        const int cb = (2 * ks + b_qp) * 8;
        uint32_t ah[2][4], al[2][4], bh[2][4], bl[2][4];
        #pragma unroll
        for (int mi = 0; mi < 2; ++mi) {
            int r = 32 * wr + 16 * mi + a_row;
            uint32_t off = K64 ? k64_off(r, ca) : k128_off(r, ca);
            LDSM4(ah[mi], AH + off);
            LDSM4(al[mi], AL + off);
        }
        #pragma unroll
        for (int nb = 0; nb < 2; ++nb) {
            int r = 32 * wc + 16 * nb + b_row;
            uint32_t off = K64 ? k64_off(r, cb) : k128_off(r, cb);
            LDSM4(bh[nb], BH + off);
            LDSM4(bl[nb], BL + off);
        }
        // term 0: hi*hi
        #pragma unroll
        for (int nb = 0; nb < 2; ++nb)
            #pragma unroll
            for (int mi = 0; mi < 2; ++mi) {
                MMA16816(d[mi][2 * nb],     ah[mi], bh[nb][0], bh[nb][1]);
                MMA16816(d[mi][2 * nb + 1], ah[mi], bh[nb][2], bh[nb][3]);
            }
        // term 1: hi*lo
        #pragma unroll
        for (int nb = 0; nb < 2; ++nb)
            #pragma unroll
            for (int mi = 0; mi < 2; ++mi) {
                MMA16816(d[mi][2 * nb],     ah[mi], bl[nb][0], bl[nb][1]);
                MMA16816(d[mi][2 * nb + 1], ah[mi], bl[nb][2], bl[nb][3]);
            }
        // term 2: lo*hi
        #pragma unroll
        for (int nb = 0; nb < 2; ++nb)
            #pragma unroll
            for (int mi = 0; mi < 2; ++mi) {
                MMA16816(d[mi][2 * nb],     al[mi], bh[nb][0], bh[nb][1]);
                MMA16816(d[mi][2 * nb + 1], al[mi], bh[nb][2], bh[nb][3]);
            }
    }
}

// ---- setup kernel: split + swizzle weights, PARALLEL (64 blocks) ----
__global__ void slam_setup(const float* __restrict__ gW1, const float* __restrict__ gW2)
{
    const int g = blockIdx.x * SETUP_TPB + threadIdx.x;   // 16384 threads
    if (g < 8192) {
        int a = g >> 7, dcol = g & 127;
        __nv_bfloat16 h, l; split_bf(gW1[g], h, l);
        uint32_t off = k64_off(dcol, a);
        *(__nv_bfloat16*)(g_w1t + off)         = h;
        *(__nv_bfloat16*)(g_w1t + 16384 + off) = l;
    }
    {
        int drow = g >> 7, k = g & 127;
        __nv_bfloat16 h, l; split_bf(gW2[g], h, l);
        uint32_t off = k128_off(k, drow);
        *(__nv_bfloat16*)(g_w2t + off)         = h;
        *(__nv_bfloat16*)(g_w2t + 32768 + off) = l;
    }
}

__global__ __launch_bounds__(TPB, 1)
void slam_mma(const float* __restrict__ x_main, const float* __restrict__ x_aux,
              const float* __restrict__ gb1, const float* __restrict__ gb2,
              float* __restrict__ out)
{
    extern __shared__ uint8_t dynraw[];
    __shared__ float sB1[128], sB2[128];

    uint8_t* dyn = (uint8_t*)(((uintptr_t)dynraw + 1023) & ~(uintptr_t)1023);
    const uint32_t sbase = smem_u32(dyn);
    const int tid = threadIdx.x, wid = tid >> 5, lane = tid & 31;
    const int wr = wid >> 2, wc = wid & 3;   // 4x4 warp grid, 32x32 tiles

    if (tid < 128) { sB1[tid] = gb1[tid]; sB2[tid] = gb2[tid]; }

    // ---- ONCE per block: copy pre-split weight tiles (plain LDG/STS — L1-warm) ----
    {
        const float4* s1 = (const float4*)g_w1t;
        float4* d1 = (float4*)(dyn + OFF_W1T);
        #pragma unroll
        for (int i = 0; i < 4; i++) d1[tid + i * TPB] = s1[tid + i * TPB];   // 32KB
        const float4* s2 = (const float4*)g_w2t;
        float4* d2 = (float4*)(dyn + OFF_W2T);
        #pragma unroll
        for (int i = 0; i < 8; i++) d2[tid + i * TPB] = s2[tid + i * TPB];   // 64KB
    }

    const int r_base = lane >> 2;             // D frag rows r_base / +8
    const int c_base = 2 * (lane & 3);        // D frag col pair
    const int st_h   = (lane >> 3) & 1;       // stmatrix lane->tile mapping
    const int st_nj  = lane >> 4;
    const int st_row = lane & 7;

    // ---- persistent loop over timesteps ----
    for (int t = blockIdx.x; t < Tn; t += GRID) {

        // X_t build: row m = 64 floats at x_aux + (m*T + t)*64  (K64 tile)
        #pragma unroll
        for (int i = 0; i < 4; i++) {
            int idx = tid + i * TPB;            // 2048 float4
            int m = idx >> 4, c = (idx & 15) * 4;
            float4 v = *(const float4*)(x_aux + ((size_t)m * Tn + t) * 64 + c);
            uint2 hi, lo; split4(v, hi, lo);
            uint32_t off = k64_off(m, c);
            *(uint2*)(dyn + OFF_XHI + off) = hi;
            *(uint2*)(dyn + OFF_XLO + off) = lo;
        }
        // main_t = x_main[3, t, 0]: natural [i][j] (K128 tile)
        {
            const float* mp = x_main + ((size_t)(3 * Tn + t)) * 16384;
            #pragma unroll
            for (int i = 0; i < 8; i++) {
                int idx = tid + i * TPB;        // 4096 float4
                int r = idx >> 5, c = (idx & 31) * 4;
                float4 v = *(const float4*)(mp + r * 128 + c);
                uint2 hi, lo; split4(v, hi, lo);
                uint32_t off = k128_off(r, c);
                *(uint2*)(dyn + OFF_MHI + off) = hi;
                *(uint2*)(dyn + OFF_MLO + off) = lo;
            }
        }
        __syncthreads();

        float d[2][4][4];

        // ---------------- Phase 1: D1[m][d] = X @ W1 ----------------
        #pragma unroll
        for (int mi = 0; mi < 2; ++mi)
            #pragma unroll
            for (int nj = 0; nj < 4; ++nj)
                #pragma unroll
                for (int q = 0; q < 4; ++q) d[mi][nj][q] = 0.f;

        gemm_phase<4, true>(sbase, OFF_XHI, OFF_XLO, OFF_W1THI, OFF_W1TLO, wr, wc, lane, d);
        __syncthreads();   // all warps done reading X before H overwrites it

        // Epilogue 1: +b1, relu, split -> H via stmatrix
        #pragma unroll
        for (int mi = 0; mi < 2; ++mi) {
            #pragma unroll
            for (int njp = 0; njp < 2; ++njp) {
                uint32_t hiR[4], loR[4];
                #pragma unroll
                for (int q = 0; q < 4; ++q) {           // q = (njoff<<1)|h
                    int nj = 2 * njp + (q >> 1), h = q & 1;
                    int col = 32 * wc + 8 * nj + c_base;
                    float f0 = fmaxf(d[mi][nj][2 * h]     + sB1[col],     0.f);
                    float f1 = fmaxf(d[mi][nj][2 * h + 1] + sB1[col + 1], 0.f);
                    split2(f0, f1, hiR[q], loR[q]);
                }
                int row = 32 * wr + 16 * mi + 8 * st_h + st_row;
                int col = 32 * wc + 8 * (2 * njp + st_nj);
                uint32_t off = k128_off(row, col);
                STM4(sbase + OFF_HHI + off, hiR);
                STM4(sbase + OFF_HLO + off, loR);
            }
        }
        __syncthreads();

        // ---------------- Phase 2: D2[k][m] = W2^T @ H^T = S^T ----------------
        #pragma unroll
        for (int mi = 0; mi < 2; ++mi)
            #pragma unroll
            for (int nj = 0; nj < 4; ++nj)
                #pragma unroll
                for (int q = 0; q < 4; ++q) d[mi][nj][q] = 0.f;

        gemm_phase<8, false>(sbase, OFF_W2THI, OFF_W2TLO, OFF_HHI, OFF_HLO, wr, wc, lane, d);
        __syncthreads();   // done reading H before S^T overwrites it

        // Epilogue 2: +b2[row k], split -> S^T via stmatrix
        #pragma unroll
        for (int mi = 0; mi < 2; ++mi) {
            const int rb = 32 * wr + 16 * mi + r_base;
            const float b2lo = sB2[rb], b2hi = sB2[rb + 8];
            #pragma unroll
            for (int njp = 0; njp < 2; ++njp) {
                uint32_t hiR[4], loR[4];
                #pragma unroll
                for (int q = 0; q < 4; ++q) {
                    int nj = 2 * njp + (q >> 1), h = q & 1;
                    float bias = h ? b2hi : b2lo;
                    float f0 = d[mi][nj][2 * h]     + bias;
                    float f1 = d[mi][nj][2 * h + 1] + bias;
                    split2(f0, f1, hiR[q], loR[q]);
                }
                int row = 32 * wr + 16 * mi + 8 * st_h + st_row;
                int col = 32 * wc + 8 * (2 * njp + st_nj);
                uint32_t off = k128_off(row, col);
                STM4(sbase + OFF_STHI + off, hiR);
                STM4(sbase + OFF_STLO + off, loR);
            }
        }
        __syncthreads();

        // ---------------- Phase 3: D3[i][k] = main @ S (B = S^T) ----------------
        #pragma unroll
        for (int mi = 0; mi < 2; ++mi)
            #pragma unroll
            for (int nj = 0; nj < 4; ++nj)
                #pragma unroll
                for (int q = 0; q < 4; ++q) d[mi][nj][q] = 0.f;

        gemm_phase<8, false>(sbase, OFF_MHI, OFF_MLO, OFF_STHI, OFF_STLO, wr, wc, lane, d);

        // Epilogue 3: direct fp32 float2 stores to gmem
        float* outT = out + (size_t)t * 16384;
        #pragma unroll
        for (int mi = 0; mi < 2; ++mi) {
            #pragma unroll
            for (int nj = 0; nj < 4; ++nj) {
                int col = 32 * wc + 8 * nj + c_base;
                #pragma unroll
                for (int h = 0; h < 2; ++h) {
                    int row = 32 * wr + 16 * mi + r_base + 8 * h;
                    float2 v; v.x = d[mi][nj][2 * h]; v.y = d[mi][nj][2 * h + 1];
                    *(float2*)&outT[row * 128 + col] = v;
                }
            }
        }
        __syncthreads();   // protect U/M regions before next iteration's builds
    }
}

extern "C" void kernel_launch(void* const* d_in, const int* in_sizes, int n_in,
                              void* d_out, int out_size)
{
    const float* x_main = (const float*)d_in[0];
    const float* x_aux  = (const float*)d_in[1];
    const float* W1     = (const float*)d_in[2];
    const float* b1     = (const float*)d_in[3];
    const float* W2     = (const float*)d_in[4];
    const float* b2     = (const float*)d_in[5];
    float* out = (float*)d_out;

    slam_setup<<<64, SETUP_TPB>>>(W1, W2);
    cudaFuncSetAttribute(slam_mma, cudaFuncAttributeMaxDynamicSharedMemorySize, DYN_BYTES);
    slam_mma<<<GRID, TPB, DYN_BYTES>>>(x_main, x_aux, b1, b2, out);
}

// round 17
// speedup vs baseline: 1.4166x; 1.0297x over previous
#include <cuda_runtime.h>
#include <cuda_bf16.h>
#include <stdint.h>

// SLAM_Layer: fused per-t 3-GEMM chain on mma.sync (bf16 HMMA), 2-term bf16 split.
//   Phase1: H   = relu(X_t @ W1 + b1)      D1[m][d], M=128 K=64  N=128
//   Phase2: S^T = W2^T @ H^T (+b2)         D2[k][m], M=128 K=128 N=128
//   Phase3: out = main_t @ S               D3[i][k], M=128 K=128 N=128 (B = S^T)
// R14 = R13 persistent body with restructured phase transitions:
//   - H lives in V (old M region) -> epilogue1 needs NO barrier (X not overwritten)
//   - M built mid-loop into V (H dead) with LDGs overlapping epi2 math
//   - 5 barriers per t instead of 6
//   - L2 prefetch of next-t X/main during the epi2 window
// Regions: W 96K | U 64K (X -> S^T) | V 64K (H -> M)  = 224KB.

#define TPB 512
#define SETUP_TPB 256
#define GRID 152
static constexpr int Tn = 1024;

// dynamic smem byte offsets
static constexpr uint32_t OFF_W1THI = 0;        // 16KB
static constexpr uint32_t OFF_W1TLO = 16384;    // 16KB
static constexpr uint32_t OFF_W1T   = 0;        // copy target (32KB contiguous)
static constexpr uint32_t OFF_W2THI = 32768;    // 32KB
static constexpr uint32_t OFF_W2TLO = 65536;    // 32KB
static constexpr uint32_t OFF_W2T   = 32768;    // copy target (64KB contiguous)
// U region (64KB): X (phase1) -> S^T (epi2..phase3)
static constexpr uint32_t OFF_XHI   = 98304;    // 16KB
static constexpr uint32_t OFF_XLO   = 114688;   // 16KB
static constexpr uint32_t OFF_STHI  = 98304;    // 32KB (over X after phase2 barrier)
static constexpr uint32_t OFF_STLO  = 131072;   // 32KB
// V region (64KB): H (epi1..phase2) -> M (epi2-window..phase3)
static constexpr uint32_t OFF_HHI   = 163840;   // 32KB
static constexpr uint32_t OFF_HLO   = 196608;   // 32KB
static constexpr uint32_t OFF_MHI   = 163840;   // 32KB (over H after phase2 barrier)
static constexpr uint32_t OFF_MLO   = 196608;   // 32KB
static constexpr uint32_t DYN_BYTES = 229376 + 1024;   // 224KB + alignment pad

// pre-split, pre-swizzled weight tiles (rewritten by setup kernel each call)
__device__ __align__(16) uint8_t g_w1t[32768];   // W1^T: hi [0,16K), lo [16K,32K)
__device__ __align__(16) uint8_t g_w2t[65536];   // W2^T: hi [0,32K), lo [32K,64K)

__device__ __forceinline__ uint32_t smem_u32(const void* p) {
    uint32_t a;
    asm("{ .reg .u64 t; cvta.to.shared.u64 t, %1; cvt.u32.u64 %0, t; }" : "=r"(a) : "l"(p));
    return a;
}

// SW128-style swizzle (writer and reader share these; bank-behavior only)
__device__ __forceinline__ uint32_t swz(uint32_t b) { return b ^ ((b >> 3) & 0x70); }
__device__ __forceinline__ uint32_t k64_off(int r, int c) {   // 128 rows x 64 bf16
    return swz((uint32_t)(r * 128 + c * 2));
}
__device__ __forceinline__ uint32_t k128_off(int r, int c) {  // 128 rows x 128 bf16
    return swz(((uint32_t)(c >> 6) << 14) + ((uint32_t)(r >> 3) << 10) +
               ((uint32_t)(r & 7) << 7) + ((uint32_t)(c & 63) << 1));
}

__device__ __forceinline__ void split_bf(float f, __nv_bfloat16& h, __nv_bfloat16& l) {
    h = __float2bfloat16_rn(f);
    l = __float2bfloat16_rn(f - __bfloat162float(h));
}
__device__ __forceinline__ void split2(float f0, float f1, uint32_t& hi, uint32_t& lo) {
    __nv_bfloat16 h0, l0, h1, l1;
    split_bf(f0, h0, l0); split_bf(f1, h1, l1);
    __nv_bfloat162 H; H.x = h0; H.y = h1;
    __nv_bfloat162 L; L.x = l0; L.y = l1;
    hi = *(uint32_t*)&H; lo = *(uint32_t*)&L;
}
__device__ __forceinline__ void split4(float4 v, uint2& hi, uint2& lo) {
    uint32_t h01, l01, h23, l23;
    split2(v.x, v.y, h01, l01);
    split2(v.z, v.w, h23, l23);
    hi.x = h01; hi.y = h23; lo.x = l01; lo.y = l23;
}

#define LDSM4(r, addr)                                                          \
    asm volatile("ldmatrix.sync.aligned.m8n8.x4.shared.b16 {%0,%1,%2,%3}, [%4];"\
        : "=r"((r)[0]), "=r"((r)[1]), "=r"((r)[2]), "=r"((r)[3]) : "r"(addr))

#define STM4(addr, r)                                                           \
    asm volatile("stmatrix.sync.aligned.m8n8.x4.shared.b16 [%0], {%1,%2,%3,%4};"\
        :: "r"(addr), "r"((r)[0]), "r"((r)[1]), "r"((r)[2]), "r"((r)[3]) : "memory")

#define MMA16816(d, a, b0, b1)                                                  \
    asm volatile("mma.sync.aligned.m16n8k16.row.col.f32.bf16.bf16.f32 "         \
        "{%0,%1,%2,%3}, {%4,%5,%6,%7}, {%8,%9}, {%0,%1,%2,%3};"                 \
        : "+f"((d)[0]), "+f"((d)[1]), "+f"((d)[2]), "+f"((d)[3])                \
        : "r"((a)[0]), "r"((a)[1]), "r"((a)[2]), "r"((a)[3]), "r"(b0), "r"(b1))

#define PREF_L2(p) asm volatile("prefetch.global.L2 [%0];" :: "l"(p))

// One phase: D += 3 split terms of A @ B^T. Warp tile 32x32. Frags loaded once/k16.
template <int NK, bool K64>
__device__ __forceinline__ void gemm_phase(uint32_t sbase,
                                           uint32_t aHi, uint32_t aLo,
                                           uint32_t bHi, uint32_t bLo,
                                           int wr, int wc, int lane,
                                           float d[2][4][4]) {
    const int a_row = lane & 15, a_qp = lane >> 4;
    const int b_row = ((lane >> 4) << 3) + (lane & 7);
    const int b_qp  = (lane >> 3) & 1;
    const uint32_t AH = sbase + aHi, AL = sbase + aLo;
    const uint32_t BH = sbase + bHi, BL = sbase + bLo;

    #pragma unroll 2
    for (int ks = 0; ks < NK; ++ks) {
        const int ca = (2 * ks + a_qp) * 8;
        const int cb = (2 * ks + b_qp) * 8;
        uint32_t ah[2][4], al[2][4], bh[2][4], bl[2][4];
        #pragma unroll
        for (int mi = 0; mi < 2; ++mi) {
            int r = 32 * wr + 16 * mi + a_row;
            uint32_t off = K64 ? k64_off(r, ca) : k128_off(r, ca);
            LDSM4(ah[mi], AH + off);
            LDSM4(al[mi], AL + off);
        }
        #pragma unroll
        for (int nb = 0; nb < 2; ++nb) {
            int r = 32 * wc + 16 * nb + b_row;
            uint32_t off = K64 ? k64_off(r, cb) : k128_off(r, cb);
            LDSM4(bh[nb], BH + off);
            LDSM4(bl[nb], BL + off);
        }
        // term 0: hi*hi
        #pragma unroll
        for (int nb = 0; nb < 2; ++nb)
            #pragma unroll
            for (int mi = 0; mi < 2; ++mi) {
                MMA16816(d[mi][2 * nb],     ah[mi], bh[nb][0], bh[nb][1]);
                MMA16816(d[mi][2 * nb + 1], ah[mi], bh[nb][2], bh[nb][3]);
            }
        // term 1: hi*lo
        #pragma unroll
        for (int nb = 0; nb < 2; ++nb)
            #pragma unroll
            for (int mi = 0; mi < 2; ++mi) {
                MMA16816(d[mi][2 * nb],     ah[mi], bl[nb][0], bl[nb][1]);
                MMA16816(d[mi][2 * nb + 1], ah[mi], bl[nb][2], bl[nb][3]);
            }
        // term 2: lo*hi
        #pragma unroll
        for (int nb = 0; nb < 2; ++nb)
            #pragma unroll
            for (int mi = 0; mi < 2; ++mi) {
                MMA16816(d[mi][2 * nb],     al[mi], bh[nb][0], bh[nb][1]);
                MMA16816(d[mi][2 * nb + 1], al[mi], bh[nb][2], bh[nb][3]);
            }
    }
}

// ---- setup kernel: split + swizzle weights, PARALLEL (64 blocks) ----
__global__ void slam_setup(const float* __restrict__ gW1, const float* __restrict__ gW2)
{
    const int g = blockIdx.x * SETUP_TPB + threadIdx.x;   // 16384 threads
    if (g < 8192) {
        int a = g >> 7, dcol = g & 127;
        __nv_bfloat16 h, l; split_bf(gW1[g], h, l);
        uint32_t off = k64_off(dcol, a);
        *(__nv_bfloat16*)(g_w1t + off)         = h;
        *(__nv_bfloat16*)(g_w1t + 16384 + off) = l;
    }
    {
        int drow = g >> 7, k = g & 127;
        __nv_bfloat16 h, l; split_bf(gW2[g], h, l);
        uint32_t off = k128_off(k, drow);
        *(__nv_bfloat16*)(g_w2t + off)         = h;
        *(__nv_bfloat16*)(g_w2t + 32768 + off) = l;
    }
}

__global__ __launch_bounds__(TPB, 1)
void slam_mma(const float* __restrict__ x_main, const float* __restrict__ x_aux,
              const float* __restrict__ gb1, const float* __restrict__ gb2,
              float* __restrict__ out)
{
    extern __shared__ uint8_t dynraw[];
    __shared__ float sB1[128], sB2[128];

    uint8_t* dyn = (uint8_t*)(((uintptr_t)dynraw + 1023) & ~(uintptr_t)1023);
    const uint32_t sbase = smem_u32(dyn);
    const int tid = threadIdx.x, wid = tid >> 5, lane = tid & 31;
    const int wr = wid >> 2, wc = wid & 3;   // 4x4 warp grid, 32x32 tiles

    if (tid < 128) { sB1[tid] = gb1[tid]; sB2[tid] = gb2[tid]; }

    // ---- ONCE per block: copy pre-split weight tiles (plain LDG/STS — L1-warm) ----
    {
        const float4* s1 = (const float4*)g_w1t;
        float4* d1 = (float4*)(dyn + OFF_W1T);
        #pragma unroll
        for (int i = 0; i < 4; i++) d1[tid + i * TPB] = s1[tid + i * TPB];   // 32KB
        const float4* s2 = (const float4*)g_w2t;
        float4* d2 = (float4*)(dyn + OFF_W2T);
        #pragma unroll
        for (int i = 0; i < 8; i++) d2[tid + i * TPB] = s2[tid + i * TPB];   // 64KB
    }

    const int r_base = lane >> 2;             // D frag rows r_base / +8
    const int c_base = 2 * (lane & 3);        // D frag col pair
    const int st_h   = (lane >> 3) & 1;       // stmatrix lane->tile mapping
    const int st_nj  = lane >> 4;
    const int st_row = lane & 7;

    // per-thread main-tile load coords (reused every iteration)
    // idx = tid + i*TPB ; r = idx>>5 ; c = (idx&31)*4
    // per-thread X load coords: idx = tid + i*TPB ; m = idx>>4 ; c = (idx&15)*4

    // ---- persistent loop over timesteps ----
    for (int t = blockIdx.x; t < Tn; t += GRID) {

        // X_t build into U (V untouched: M(t-1) dead after prior loop-end barrier)
        #pragma unroll
        for (int i = 0; i < 4; i++) {
            int idx = tid + i * TPB;            // 2048 float4
            int m = idx >> 4, c = (idx & 15) * 4;
            float4 v = *(const float4*)(x_aux + ((size_t)m * Tn + t) * 64 + c);
            uint2 hi, lo; split4(v, hi, lo);
            uint32_t off = k64_off(m, c);
            *(uint2*)(dyn + OFF_XHI + off) = hi;
            *(uint2*)(dyn + OFF_XLO + off) = lo;
        }
        __syncthreads();                        // [A] X ready

        float d[2][4][4];

        // ---------------- Phase 1: D1[m][d] = X @ W1 ----------------
        #pragma unroll
        for (int mi = 0; mi < 2; ++mi)
            #pragma unroll
            for (int nj = 0; nj < 4; ++nj)
                #pragma unroll
                for (int q = 0; q < 4; ++q) d[mi][nj][q] = 0.f;

        gemm_phase<4, true>(sbase, OFF_XHI, OFF_XLO, OFF_W1THI, OFF_W1TLO, wr, wc, lane, d);

        // Epilogue 1 (NO barrier: H goes to V, phase1 stragglers read U/W only)
        #pragma unroll
        for (int mi = 0; mi < 2; ++mi) {
            #pragma unroll
            for (int njp = 0; njp < 2; ++njp) {
                uint32_t hiR[4], loR[4];
                #pragma unroll
                for (int q = 0; q < 4; ++q) {           // q = (njoff<<1)|h
                    int nj = 2 * njp + (q >> 1), h = q & 1;
                    int col = 32 * wc + 8 * nj + c_base;
                    float f0 = fmaxf(d[mi][nj][2 * h]     + sB1[col],     0.f);
                    float f1 = fmaxf(d[mi][nj][2 * h + 1] + sB1[col + 1], 0.f);
                    split2(f0, f1, hiR[q], loR[q]);
                }
                int row = 32 * wr + 16 * mi + 8 * st_h + st_row;
                int col = 32 * wc + 8 * (2 * njp + st_nj);
                uint32_t off = k128_off(row, col);
                STM4(sbase + OFF_HHI + off, hiR);
                STM4(sbase + OFF_HLO + off, loR);
            }
        }
        __syncthreads();                        // [B] H ready

        // ---------------- Phase 2: D2[k][m] = W2^T @ H^T = S^T ----------------
        #pragma unroll
        for (int mi = 0; mi < 2; ++mi)
            #pragma unroll
            for (int nj = 0; nj < 4; ++nj)
                #pragma unroll
                for (int q = 0; q < 4; ++q) d[mi][nj][q] = 0.f;

        gemm_phase<8, false>(sbase, OFF_W2THI, OFF_W2TLO, OFF_HHI, OFF_HLO, wr, wc, lane, d);
        __syncthreads();                        // [C] all warps done with H and X

        // ---- overlap window: epi2 (S^T -> U) + M build (-> V) + t+1 prefetch ----
        {
            const float* mp = x_main + ((size_t)(3 * Tn + t)) * 16384;

            // chunk 0: issue 4 main LDGs, then epi2 mi=0 math overlaps their latency
            float4 mv[4];
            #pragma unroll
            for (int i = 0; i < 4; i++) {
                int idx = tid + i * TPB;
                mv[i] = *(const float4*)(mp + (idx >> 5) * 128 + (idx & 31) * 4);
            }
            {
                const int mi = 0;
                const int rb = 32 * wr + 16 * mi + r_base;
                const float b2lo = sB2[rb], b2hi = sB2[rb + 8];
                #pragma unroll
                for (int njp = 0; njp < 2; ++njp) {
                    uint32_t hiR[4], loR[4];
                    #pragma unroll
                    for (int q = 0; q < 4; ++q) {
                        int nj = 2 * njp + (q >> 1), h = q & 1;
                        float bias = h ? b2hi : b2lo;
                        split2(d[mi][nj][2 * h] + bias, d[mi][nj][2 * h + 1] + bias,
                               hiR[q], loR[q]);
                    }
                    int row = 32 * wr + 16 * mi + 8 * st_h + st_row;
                    int col = 32 * wc + 8 * (2 * njp + st_nj);
                    uint32_t off = k128_off(row, col);
                    STM4(sbase + OFF_STHI + off, hiR);
                    STM4(sbase + OFF_STLO + off, loR);
                }
            }
            #pragma unroll
            for (int i = 0; i < 4; i++) {
                int idx = tid + i * TPB;
                uint2 hi, lo; split4(mv[i], hi, lo);
                uint32_t off = k128_off(idx >> 5, (idx & 31) * 4);
                *(uint2*)(dyn + OFF_MHI + off) = hi;
                *(uint2*)(dyn + OFF_MLO + off) = lo;
            }

            // chunk 1: next 4 main LDGs + epi2 mi=1
            float4 mw[4];
            #pragma unroll
            for (int i = 4; i < 8; i++) {
                int idx = tid + i * TPB;
                mw[i - 4] = *(const float4*)(mp + (idx >> 5) * 128 + (idx & 31) * 4);
            }
            {
                const int mi = 1;
                const int rb = 32 * wr + 16 * mi + r_base;
                const float b2lo = sB2[rb], b2hi = sB2[rb + 8];
                #pragma unroll
                for (int njp = 0; njp < 2; ++njp) {
                    uint32_t hiR[4], loR[4];
                    #pragma unroll
                    for (int q = 0; q < 4; ++q) {
                        int nj = 2 * njp + (q >> 1), h = q & 1;
                        float bias = h ? b2hi : b2lo;
                        split2(d[mi][nj][2 * h] + bias, d[mi][nj][2 * h + 1] + bias,
                               hiR[q], loR[q]);
                    }
                    int row = 32 * wr + 16 * mi + 8 * st_h + st_row;
                    int col = 32 * wc + 8 * (2 * njp + st_nj);
                    uint32_t off = k128_off(row, col);
                    STM4(sbase + OFF_STHI + off, hiR);
                    STM4(sbase + OFF_STLO + off, loR);
                }
            }
            #pragma unroll
            for (int i = 4; i < 8; i++) {
                int idx = tid + i * TPB;
                uint2 hi, lo; split4(mw[i - 4], hi, lo);
                uint32_t off = k128_off(idx >> 5, (idx & 31) * 4);
                *(uint2*)(dyn + OFF_MHI + off) = hi;
                *(uint2*)(dyn + OFF_MLO + off) = lo;
            }

            // prefetch next iteration's X and main lines into L2
            int tn = t + GRID;
            if (tn < Tn) {
                #pragma unroll
                for (int i = 0; i < 4; i++) {
                    int idx = tid + i * TPB;
                    PREF_L2(x_aux + ((size_t)(idx >> 4) * Tn + tn) * 64 + (idx & 15) * 4);
                }
                const float* mp2 = x_main + ((size_t)(3 * Tn + tn)) * 16384;
                #pragma unroll
                for (int i = 0; i < 8; i++) {
                    int idx = tid + i * TPB;
                    PREF_L2(mp2 + (idx >> 5) * 128 + (idx & 31) * 4);
                }
            }
        }
        __syncthreads();                        // [D] S^T + M ready

        // ---------------- Phase 3: D3[i][k] = main @ S (B = S^T) ----------------
        #pragma unroll
        for (int mi = 0; mi < 2; ++mi)
            #pragma unroll
            for (int nj = 0; nj < 4; ++nj)
                #pragma unroll
                for (int q = 0; q < 4; ++q) d[mi][nj][q] = 0.f;

        gemm_phase<8, false>(sbase, OFF_MHI, OFF_MLO, OFF_STHI, OFF_STLO, wr, wc, lane, d);

        // Epilogue 3: direct fp32 float2 stores to gmem
        float* outT = out + (size_t)t * 16384;
        #pragma unroll
        for (int mi = 0; mi < 2; ++mi) {
            #pragma unroll
            for (int nj = 0; nj < 4; ++nj) {
                int col = 32 * wc + 8 * nj + c_base;
                #pragma unroll
                for (int h = 0; h < 2; ++h) {
                    int row = 32 * wr + 16 * mi + r_base + 8 * h;
                    float2 v; v.x = d[mi][nj][2 * h]; v.y = d[mi][nj][2 * h + 1];
                    *(float2*)&outT[row * 128 + col] = v;
                }
            }
        }
        __syncthreads();                        // [E] protect U/V before next builds
    }
}

extern "C" void kernel_launch(void* const* d_in, const int* in_sizes, int n_in,
                              void* d_out, int out_size)
{
    const float* x_main = (const float*)d_in[0];
    const float* x_aux  = (const float*)d_in[1];
    const float* W1     = (const float*)d_in[2];
    const float* b1     = (const float*)d_in[3];
    const float* W2     = (const float*)d_in[4];
    const float* b2     = (const float*)d_in[5];
    float* out = (float*)d_out;

    slam_setup<<<64, SETUP_TPB>>>(W1, W2);
    cudaFuncSetAttribute(slam_mma, cudaFuncAttributeMaxDynamicSharedMemorySize, DYN_BYTES);
    slam_mma<<<GRID, TPB, DYN_BYTES>>>(x_main, x_aux, b1, b2, out);
}